// round 1
// baseline (speedup 1.0000x reference)
#include <cuda_runtime.h>
#include <cuda_bf16.h>
#include <math.h>

// Problem constants (fixed shapes per reference):
//   support: [5, 196, 384]   query: [512, 196, 384]
//   out:     [1, 512, 5]  = scale * (top6sum + bias)
#define NC 5
#define M  512
#define P  196
#define D  384

#define NEG_BIG (-1.0e30f)

// Scratch: inverse norms (allocation-free rule -> __device__ globals)
__device__ float g_inv_s[NC * P];       // 980
__device__ float g_inv_q[M * P];        // 100352

// ---------------------------------------------------------------------------
// Kernel 1: inverse L2 norms, one warp per row. eps matches F.normalize:
// inv = 1 / max(||x||_2, 1e-12)
// ---------------------------------------------------------------------------
__global__ void inv_norm_kernel(const float* __restrict__ support,
                                const float* __restrict__ query) {
    const int warp = (blockIdx.x * blockDim.x + threadIdx.x) >> 5;
    const int lane = threadIdx.x & 31;
    const int n_rows = NC * P + M * P;
    if (warp >= n_rows) return;

    const float* row;
    if (warp < NC * P) row = support + (size_t)warp * D;
    else               row = query + (size_t)(warp - NC * P) * D;

    float s = 0.0f;
    #pragma unroll
    for (int j = 0; j < D / 32; ++j) {
        float x = row[lane + 32 * j];
        s += x * x;
    }
    #pragma unroll
    for (int off = 16; off; off >>= 1)
        s += __shfl_xor_sync(0xffffffffu, s, off);

    if (lane == 0) {
        float inv = 1.0f / fmaxf(sqrtf(s), 1e-12f);
        if (warp < NC * P) g_inv_s[warp]          = inv;
        else               g_inv_q[warp - NC * P] = inv;
    }
}

// ---------------------------------------------------------------------------
// Kernel 2: per (m,c): C = Qn[196,384] * Sn^T -> rowmax over support patches
//           -> top-6 sum over query patches -> scale*(sum+bias).
// CTA: 256 threads (16 tx x 16 ty). Each thread: 13(p) x 4(q) register tile.
// q tiled 4x64; d tiled 12x32 via padded smem (stride 33 => conflict-free,
// with broadcast reuse across tx for A and across ty for B).
// ---------------------------------------------------------------------------
__global__ __launch_bounds__(256, 2)
void protonet_main_kernel(const float* __restrict__ support,
                          const float* __restrict__ query,
                          const float* __restrict__ scale_cls,
                          const float* __restrict__ bias,
                          float* __restrict__ out) {
    const int c = blockIdx.x;   // class  0..4
    const int m = blockIdx.y;   // query image 0..511

    const int tx = threadIdx.x & 15;
    const int ty = threadIdx.x >> 4;

    __shared__ float As[208][33];   // query rows (p), padded to 208
    __shared__ float Bs[64][33];    // support rows (q tile)
    __shared__ float pmax[208];

    const float* __restrict__ qptr = query   + (size_t)m * P * D;
    const float* __restrict__ sptr = support + (size_t)c * P * D;
    const float* __restrict__ invq = g_inv_q + m * P;
    const float* __restrict__ invs = g_inv_s + c * P;

    float rmax[13];
    #pragma unroll
    for (int i = 0; i < 13; ++i) rmax[i] = NEG_BIG;

    for (int qt = 0; qt < 4; ++qt) {
        const int q0 = qt * 64;

        float acc[13][4];
        #pragma unroll
        for (int i = 0; i < 13; ++i)
            #pragma unroll
            for (int j = 0; j < 4; ++j) acc[i][j] = 0.0f;

        for (int t = 0; t < D / 32; ++t) {
            const int k0 = t * 32;
            __syncthreads();   // previous tile's compute done before overwrite

            // Load A chunk: 208 rows x 32 cols (rows >= 196 zero), float4 loads
            for (int idx = threadIdx.x; idx < 208 * 8; idx += 256) {
                const int row = idx >> 3;
                const int c4  = (idx & 7) << 2;
                float4 v = make_float4(0.f, 0.f, 0.f, 0.f);
                if (row < P) {
                    v = *reinterpret_cast<const float4*>(qptr + (size_t)row * D + k0 + c4);
                    const float s = invq[row];
                    v.x *= s; v.y *= s; v.z *= s; v.w *= s;
                }
                float* dst = &As[row][c4];
                dst[0] = v.x; dst[1] = v.y; dst[2] = v.z; dst[3] = v.w;
            }
            // Load B chunk: 64 rows x 32 cols (global q row >= 196 -> zero)
            for (int idx = threadIdx.x; idx < 64 * 8; idx += 256) {
                const int row  = idx >> 3;
                const int c4   = (idx & 7) << 2;
                const int qrow = q0 + row;
                float4 v = make_float4(0.f, 0.f, 0.f, 0.f);
                if (qrow < P) {
                    v = *reinterpret_cast<const float4*>(sptr + (size_t)qrow * D + k0 + c4);
                    const float s = invs[qrow];
                    v.x *= s; v.y *= s; v.z *= s; v.w *= s;
                }
                float* dst = &Bs[row][c4];
                dst[0] = v.x; dst[1] = v.y; dst[2] = v.z; dst[3] = v.w;
            }
            __syncthreads();

            #pragma unroll
            for (int kk = 0; kk < 32; ++kk) {
                float a[13], b[4];
                #pragma unroll
                for (int i = 0; i < 13; ++i) a[i] = As[ty + 16 * i][kk];
                #pragma unroll
                for (int j = 0; j < 4; ++j)  b[j] = Bs[tx + 16 * j][kk];
                #pragma unroll
                for (int i = 0; i < 13; ++i)
                    #pragma unroll
                    for (int j = 0; j < 4; ++j)
                        acc[i][j] = fmaf(a[i], b[j], acc[i][j]);
            }
        }

        // Fold this q-tile into the running max (mask padded q columns)
        #pragma unroll
        for (int j = 0; j < 4; ++j) {
            if (q0 + tx + 16 * j < P) {
                #pragma unroll
                for (int i = 0; i < 13; ++i)
                    rmax[i] = fmaxf(rmax[i], acc[i][j]);
            }
        }
    }

    // Reduce max across the 16 tx threads (lane bits 0..3)
    #pragma unroll
    for (int off = 8; off >= 1; off >>= 1) {
        #pragma unroll
        for (int i = 0; i < 13; ++i)
            rmax[i] = fmaxf(rmax[i], __shfl_xor_sync(0xffffffffu, rmax[i], off));
    }
    if (tx == 0) {
        #pragma unroll
        for (int i = 0; i < 13; ++i)
            pmax[ty + 16 * i] = rmax[i];
    }
    __syncthreads();

    // Warp 0: exact top-6 sum over pmax[0..195]
    if (threadIdx.x < 32) {
        const int lane = threadIdx.x;
        float v[7];
        #pragma unroll
        for (int k = 0; k < 7; ++k) {
            const int p = lane + 32 * k;
            v[k] = (p < P) ? pmax[p] : NEG_BIG;
        }
        float total = 0.0f;
        for (int it = 0; it < 6; ++it) {
            float bv = NEG_BIG; int bk = 0;
            #pragma unroll
            for (int k = 0; k < 7; ++k)
                if (v[k] > bv) { bv = v[k]; bk = k; }
            int bi = lane + 32 * bk;
            #pragma unroll
            for (int off = 16; off; off >>= 1) {
                float ov = __shfl_xor_sync(0xffffffffu, bv, off);
                int   oi = __shfl_xor_sync(0xffffffffu, bi, off);
                if (ov > bv || (ov == bv && oi < bi)) { bv = ov; bi = oi; }
            }
            total += bv;
            if ((bi & 31) == lane) v[bi >> 5] = NEG_BIG;
        }
        if (lane == 0)
            out[m * NC + c] = scale_cls[0] * (total + bias[0]);
    }
}

// ---------------------------------------------------------------------------
extern "C" void kernel_launch(void* const* d_in, const int* in_sizes, int n_in,
                              void* d_out, int out_size) {
    const float* support   = (const float*)d_in[0];
    const float* query     = (const float*)d_in[1];
    const float* scale_cls = (const float*)d_in[2];
    const float* bias      = (const float*)d_in[3];
    float* out = (float*)d_out;

    // Kernel 1: inverse norms (one warp per row)
    const int n_rows = NC * P + M * P;                // 101332
    const int threads = 256;
    const int warps_per_block = threads / 32;
    const int blocks = (n_rows + warps_per_block - 1) / warps_per_block;
    inv_norm_kernel<<<blocks, threads>>>(support, query);

    // Kernel 2: fused GEMM + max + top6
    dim3 grid(NC, M);
    protonet_main_kernel<<<grid, 256>>>(support, query, scale_cls, bias, out);
}

// round 5
// speedup vs baseline: 7.4448x; 7.4448x over previous
#include <cuda_runtime.h>
#include <cuda_bf16.h>
#include <cstdint>
#include <math.h>

// Shapes: support [5,196,384], query [512,196,384], out [1,512,5]
#define NC 5
#define M_IMG 512
#define P 196
#define D 384

#define NEG_BIG (-1.0e30f)

#define AR 208              // staged A rows (13 m16 tiles)
#define SROWS 256           // padded support rows per class in g_sbf (zero-init)
#define A_TILE_STRIDE 26624 // 208 rows * 128B per k-tile
#define B_TILE_STRIDE 8192  // 64 rows * 128B per k-tile

// smem layout (dynamic): [0..832) pmax | [1024..160768) A | [160768..209920) B
#define SM_A 1024
#define SM_B 160768
#define SM_TOTAL 209920

// ---------------- staged data (allocation-free: __device__ globals) -----------
// query: raw bf16 (+64 zero pad rows so A row reads up to 207 are safe for m=511)
__device__ __align__(16) __nv_bfloat16 g_qbf[(M_IMG * P + 64) * D];
// support: L2-normalized bf16, padded to 256 rows/class (pad rows stay zero)
__device__ __align__(16) __nv_bfloat16 g_sbf[NC * SROWS * D];
// inverse L2 norm of each query row
__device__ float g_invq[M_IMG * P];

// ---------------- PTX helpers -------------------------------------------------
__device__ __forceinline__ uint32_t smem_u32(const void* p) {
    uint32_t a;
    asm("{ .reg .u64 t; cvta.to.shared.u64 t, %1; cvt.u32.u64 %0, t; }" : "=r"(a) : "l"(p));
    return a;
}
#define SW128(o) ((o) ^ (((o) >> 3) & 0x70))

__device__ __forceinline__ void cp_async16(uint32_t dst, const void* src) {
    asm volatile("cp.async.cg.shared.global [%0], [%1], 16;" :: "r"(dst), "l"(src));
}
__device__ __forceinline__ void cp_commit() { asm volatile("cp.async.commit_group;" ::: "memory"); }
template <int N>
__device__ __forceinline__ void cp_wait_n() {
    asm volatile("cp.async.wait_group %0;" :: "n"(N) : "memory");
}

#define LDSM_X4(r, addr) \
    asm volatile("ldmatrix.sync.aligned.m8n8.x4.shared.b16 {%0,%1,%2,%3}, [%4];" \
        : "=r"((r)[0]), "=r"((r)[1]), "=r"((r)[2]), "=r"((r)[3]) : "r"(addr))

#define MMA16816(c, a, b0, b1) \
    asm volatile("mma.sync.aligned.m16n8k16.row.col.f32.bf16.bf16.f32 " \
        "{%0,%1,%2,%3}, {%4,%5,%6,%7}, {%8,%9}, {%0,%1,%2,%3};" \
        : "+f"((c)[0]), "+f"((c)[1]), "+f"((c)[2]), "+f"((c)[3]) \
        : "r"((a)[0]), "r"((a)[1]), "r"((a)[2]), "r"((a)[3]), "r"(b0), "r"(b1))

// ---------------- Kernel 1: norms + bf16 staging ------------------------------
__global__ void stage_kernel(const float* __restrict__ support,
                             const float* __restrict__ query) {
    const int warp = (blockIdx.x * blockDim.x + threadIdx.x) >> 5;
    const int lane = threadIdx.x & 31;
    const int nq = M_IMG * P;
    const int nrows = nq + NC * P;
    if (warp >= nrows) return;

    const bool is_q = (warp < nq);
    const float* src = is_q ? (query + (size_t)warp * D)
                            : (support + (size_t)(warp - nq) * D);

    float4 v[3];
    float s = 0.0f;
    #pragma unroll
    for (int j = 0; j < 3; ++j) {
        v[j] = reinterpret_cast<const float4*>(src)[lane + 32 * j];
        s += v[j].x * v[j].x + v[j].y * v[j].y + v[j].z * v[j].z + v[j].w * v[j].w;
    }
    #pragma unroll
    for (int off = 16; off; off >>= 1) s += __shfl_xor_sync(0xffffffffu, s, off);
    const float inv = 1.0f / fmaxf(sqrtf(s), 1e-12f);

    if (is_q) {
        uint32_t* dst = reinterpret_cast<uint32_t*>(g_qbf + (size_t)warp * D);
        #pragma unroll
        for (int j = 0; j < 3; ++j) {
            const int k = lane + 32 * j;
            __nv_bfloat162 a = __floats2bfloat162_rn(v[j].x, v[j].y);
            __nv_bfloat162 b = __floats2bfloat162_rn(v[j].z, v[j].w);
            dst[2 * k]     = *reinterpret_cast<uint32_t*>(&a);
            dst[2 * k + 1] = *reinterpret_cast<uint32_t*>(&b);
        }
        if (lane == 0) g_invq[warp] = inv;
    } else {
        const int sr = warp - nq;
        const int c = sr / P, p = sr % P;
        uint32_t* dst = reinterpret_cast<uint32_t*>(g_sbf + ((size_t)c * SROWS + p) * D);
        #pragma unroll
        for (int j = 0; j < 3; ++j) {
            const int k = lane + 32 * j;
            __nv_bfloat162 a = __floats2bfloat162_rn(v[j].x * inv, v[j].y * inv);
            __nv_bfloat162 b = __floats2bfloat162_rn(v[j].z * inv, v[j].w * inv);
            dst[2 * k]     = *reinterpret_cast<uint32_t*>(&a);
            dst[2 * k + 1] = *reinterpret_cast<uint32_t*>(&b);
        }
    }
}

// ---------------- per-warp HMMA tile step ------------------------------------
// One k-tile (64 cols = 4 k16 steps) for MT m16-tiles x 64 support cols.
template <int MT>
__device__ __forceinline__ void gemm_kt(uint32_t a_region, uint32_t b_region, int kt,
                                        int row_base, int lane, float (&c)[4][8][4]) {
    const int l7 = lane & 7;
    const int a_row = (((lane >> 3) & 1) << 3) + l7;   // within m-tile
    const int a_kb  = ((lane >> 4) & 1) << 4;          // +0 / +16 bytes
    const int b_row = ((lane >> 4) << 3) + l7;         // within n16 group
    const int b_kb  = ((lane >> 3) & 1) << 4;
    const uint32_t abase = a_region + kt * A_TILE_STRIDE;
    const uint32_t bbase = b_region + kt * B_TILE_STRIDE;

    #pragma unroll
    for (int k16 = 0; k16 < 4; ++k16) {
        const int kb = k16 * 32;
        uint32_t a[4][4];
        #pragma unroll
        for (int mt = 0; mt < MT; ++mt) {
            const int o = (row_base + mt * 16 + a_row) * 128 + kb + a_kb;
            LDSM_X4(a[mt], abase + SW128(o));
        }
        uint32_t b[4][4];
        #pragma unroll
        for (int j = 0; j < 4; ++j) {
            const int o = (j * 16 + b_row) * 128 + kb + b_kb;
            LDSM_X4(b[j], bbase + SW128(o));
        }
        #pragma unroll
        for (int mt = 0; mt < MT; ++mt)
            #pragma unroll
            for (int n8 = 0; n8 < 8; ++n8)
                MMA16816(c[mt][n8], a[mt],
                         b[n8 >> 1][(n8 & 1) * 2], b[n8 >> 1][(n8 & 1) * 2 + 1]);
    }
}

template <int MT>
__device__ __forceinline__ void fold_max(int lane, int nc, float (&c)[4][8][4],
                                         float (&rmax)[4][2]) {
    const int col0 = nc * 64 + ((lane & 3) << 1);
    #pragma unroll
    for (int mt = 0; mt < MT; ++mt)
        #pragma unroll
        for (int n8 = 0; n8 < 8; ++n8) {
            if (col0 + n8 * 8 < P) {   // cols col, col+1 both < 196 (even boundary)
                rmax[mt][0] = fmaxf(rmax[mt][0], fmaxf(c[mt][n8][0], c[mt][n8][1]));
                rmax[mt][1] = fmaxf(rmax[mt][1], fmaxf(c[mt][n8][2], c[mt][n8][3]));
            }
        }
}

// Compile-time k-tile loop: each step needs a LITERAL wait_group immediate.
// __syncthreads stays at a block-uniform point (outside the wid branch).
template <int KT>
__device__ __forceinline__ void kt_loop(uint32_t smb, int wid, int row_base, int lane,
                                        float (&cacc)[4][8][4]) {
    if constexpr (KT < 6) {
        cp_wait_n<5 - KT>();       // B k-tile KT arrived (A done by first wait)
        __syncthreads();
        if (wid == 0) gemm_kt<4>(smb + SM_A, smb + SM_B, KT, row_base, lane, cacc);
        else          gemm_kt<3>(smb + SM_A, smb + SM_B, KT, row_base, lane, cacc);
        kt_loop<KT + 1>(smb, wid, row_base, lane, cacc);
    }
}

// ---------------- Kernel 2: fused HMMA GEMM + max + top6 ----------------------
__global__ __launch_bounds__(128, 1)
void protonet_hmma_kernel(const float* __restrict__ scale_cls,
                          const float* __restrict__ bias,
                          float* __restrict__ out) {
    extern __shared__ char sm[];
    const uint32_t smb = smem_u32(sm);
    float* pmax = reinterpret_cast<float*>(sm);
    const int tid = threadIdx.x;
    const int wid = tid >> 5;
    const int lane = tid & 31;
    const int c = blockIdx.x;   // class fast -> query tile L2 reuse
    const int m = blockIdx.y;

    const __nv_bfloat16* qbase = g_qbf + (size_t)m * P * D;
    const __nv_bfloat16* sbase = g_sbf + (size_t)c * SROWS * D;

    // ---- stage A once: 208 rows x 384 cols bf16, SW128, k-tiled ----
    for (int idx = tid; idx < AR * 8 * 6; idx += 128) {     // 9984 x 16B
        const int kt  = idx / (AR * 8);
        const int rem = idx - kt * (AR * 8);
        const int row = rem >> 3;
        const int cb  = (rem & 7) << 4;
        const void* src = qbase + (size_t)row * D + kt * 64 + (cb >> 1);
        cp_async16(smb + SM_A + kt * A_TILE_STRIDE + SW128(row * 128 + cb), src);
    }
    cp_commit();

    // warp m-tile assignment: wid0 -> 4 tiles (rows 0..63), wid1..3 -> 3 tiles
    const int mtc = (wid == 0) ? 4 : 3;
    const int row_base = (wid == 0) ? 0 : (64 + (wid - 1) * 48);

    float rmax[4][2];
    #pragma unroll
    for (int i = 0; i < 4; ++i) { rmax[i][0] = NEG_BIG; rmax[i][1] = NEG_BIG; }

    for (int nc = 0; nc < 4; ++nc) {
        if (nc) __syncthreads();   // previous chunk's B reads done before overwrite

        // issue B loads k-tile by k-tile (6 commit groups -> overlap with compute)
        #pragma unroll
        for (int kt = 0; kt < 6; ++kt) {
            for (int idx = tid; idx < 512; idx += 128) {    // 64 rows x 8 x 16B
                const int row = idx >> 3;
                const int cb  = (idx & 7) << 4;
                const void* src = sbase + (size_t)(nc * 64 + row) * D + kt * 64 + (cb >> 1);
                cp_async16(smb + SM_B + kt * B_TILE_STRIDE + SW128(row * 128 + cb), src);
            }
            cp_commit();
        }

        float cacc[4][8][4];
        #pragma unroll
        for (int i = 0; i < 4; ++i)
            #pragma unroll
            for (int j = 0; j < 8; ++j)
                #pragma unroll
                for (int k = 0; k < 4; ++k) cacc[i][j][k] = 0.0f;

        kt_loop<0>(smb, wid, row_base, lane, cacc);

        if (wid == 0) fold_max<4>(lane, nc, cacc, rmax);
        else          fold_max<3>(lane, nc, cacc, rmax);
    }

    // ---- reduce col-max across the 4 lanes sharing a row; apply invq ----
    const float* invq = g_invq + (size_t)m * P;
    #pragma unroll
    for (int mt = 0; mt < 4; ++mt) {
        float v0 = rmax[mt][0], v1 = rmax[mt][1];
        #pragma unroll
        for (int off = 1; off <= 2; off <<= 1) {
            v0 = fmaxf(v0, __shfl_xor_sync(0xffffffffu, v0, off));
            v1 = fmaxf(v1, __shfl_xor_sync(0xffffffffu, v1, off));
        }
        if ((lane & 3) == 0 && mt < mtc) {
            const int g = lane >> 2;
            const int r0 = row_base + mt * 16 + g;
            const int r1 = r0 + 8;
            if (r0 < P) pmax[r0] = v0 * invq[r0];
            if (r1 < P) pmax[r1] = v1 * invq[r1];
        }
    }
    __syncthreads();

    // ---- warp 0: exact top-6 over pmax[0..195] ----
    if (wid == 0) {
        float v[7];
        #pragma unroll
        for (int k = 0; k < 7; ++k) {
            const int p = lane + 32 * k;
            v[k] = (p < P) ? pmax[p] : NEG_BIG;
        }
        float total = 0.0f;
        for (int it = 0; it < 6; ++it) {
            float bv = NEG_BIG; int bk = 0;
            #pragma unroll
            for (int k = 0; k < 7; ++k)
                if (v[k] > bv) { bv = v[k]; bk = k; }
            int bi = lane + 32 * bk;
            #pragma unroll
            for (int off = 16; off; off >>= 1) {
                float ov = __shfl_xor_sync(0xffffffffu, bv, off);
                int   oi = __shfl_xor_sync(0xffffffffu, bi, off);
                if (ov > bv || (ov == bv && oi < bi)) { bv = ov; bi = oi; }
            }
            total += bv;
            if ((bi & 31) == lane) v[bi >> 5] = NEG_BIG;
        }
        if (lane == 0) out[m * NC + c] = scale_cls[0] * (total + bias[0]);
    }
}

// ---------------------------------------------------------------------------
extern "C" void kernel_launch(void* const* d_in, const int* in_sizes, int n_in,
                              void* d_out, int out_size) {
    const float* support   = (const float*)d_in[0];
    const float* query     = (const float*)d_in[1];
    const float* scale_cls = (const float*)d_in[2];
    const float* bias      = (const float*)d_in[3];
    float* out = (float*)d_out;

    // Stage 1: norms + bf16 conversion
    const int nrows = M_IMG * P + NC * P;
    const int blocks = (nrows * 32 + 255) / 256;
    stage_kernel<<<blocks, 256>>>(support, query);

    // Stage 2: fused HMMA GEMM + reductions (set attribute every call; capture-safe)
    cudaFuncSetAttribute(protonet_hmma_kernel,
                         cudaFuncAttributeMaxDynamicSharedMemorySize, SM_TOTAL);
    dim3 grid(NC, M_IMG);
    protonet_hmma_kernel<<<grid, 128, SM_TOTAL>>>(scale_cls, bias, out);
}